// round 1
// baseline (speedup 1.0000x reference)
#include <cuda_runtime.h>
#include <math.h>

#define BATCH   32
#define HEADS   8
#define SEQ     512
#define DMODEL  1024
#define DHEAD   128
#define DCOL    18
#define BHS     (BATCH*HEADS)   // 256

// ---------------- scratch (static device globals; no allocation) ----------------
__device__ __align__(256) float g_fhead[(size_t)BHS*SEQ*DHEAD];   // [b,h,q,dh]
__device__ __align__(256) float g_ftail[(size_t)BHS*SEQ*DHEAD];   // [b,h,k,dh]
__device__ __align__(256) float g_fvT  [(size_t)BHS*DHEAD*SEQ];   // [b,h,dh,k]  (transposed V)
__device__ __align__(256) float g_adjm [(size_t)HEADS*SEQ*SEQ];   // (1-adj)*(-10000)
__device__ __align__(256) float g_attn [(size_t)BATCH*SEQ*DMODEL];// [b,q,h*dh]

// ---------------- helpers ----------------
__device__ __forceinline__ unsigned f2tf32(float f) {
    unsigned u;
    asm("cvt.rna.tf32.f32 %0, %1;" : "=r"(u) : "f"(f));
    return u;
}

__device__ __forceinline__ void mma8(float* c, const unsigned* a, const unsigned* b) {
    asm volatile(
        "mma.sync.aligned.m16n8k8.row.col.f32.tf32.tf32.f32 "
        "{%0,%1,%2,%3}, {%4,%5,%6,%7}, {%8,%9}, {%0,%1,%2,%3};\n"
        : "+f"(c[0]), "+f"(c[1]), "+f"(c[2]), "+f"(c[3])
        : "r"(a[0]), "r"(a[1]), "r"(a[2]), "r"(a[3]), "r"(b[0]), "r"(b[1]));
}

// ---------------- adjacency: softmax(col_head @ col_tail^T, diag=0) ----------------
// writes g_adjm[h,q,k] = (1 - adj) * (-10000)  (matches reference arithmetic exactly)
__global__ void adj_kernel(const float* __restrict__ col_head,
                           const float* __restrict__ col_tail)
{
    const int q = blockIdx.x;
    const int h = blockIdx.y;
    const int t = threadIdx.x;                 // 128 threads
    __shared__ float ch[DCOL];
    __shared__ float sred[4];

    if (t < DCOL) ch[t] = col_head[((size_t)h*SEQ + q)*DCOL + t];
    __syncthreads();

    float l[4];
#pragma unroll
    for (int i = 0; i < 4; i++) {
        const int k = t + i*128;
        const float* ct = col_tail + ((size_t)h*SEQ + k)*DCOL;
        float s = 0.f;
#pragma unroll
        for (int c = 0; c < DCOL; c++) s += ch[c]*ct[c];
        l[i] = (k == q) ? 0.f : s;             // zero diagonal BEFORE softmax
    }

    float mx = fmaxf(fmaxf(l[0],l[1]), fmaxf(l[2],l[3]));
#pragma unroll
    for (int o = 16; o; o >>= 1) mx = fmaxf(mx, __shfl_xor_sync(0xffffffffu, mx, o));
    if ((t & 31) == 0) sred[t >> 5] = mx;
    __syncthreads();
    mx = fmaxf(fmaxf(sred[0],sred[1]), fmaxf(sred[2],sred[3]));
    __syncthreads();

    float e[4]; float sum = 0.f;
#pragma unroll
    for (int i = 0; i < 4; i++) { e[i] = expf(l[i]-mx); sum += e[i]; }
#pragma unroll
    for (int o = 16; o; o >>= 1) sum += __shfl_xor_sync(0xffffffffu, sum, o);
    if ((t & 31) == 0) sred[t >> 5] = sum;
    __syncthreads();
    sum = sred[0]+sred[1]+sred[2]+sred[3];
    const float inv = 1.f/sum;

    float* dst = g_adjm + ((size_t)h*SEQ + q)*SEQ;
#pragma unroll
    for (int i = 0; i < 4; i++) {
        const int k = t + i*128;
        dst[k] = (1.f - e[i]*inv) * (-10000.f);
    }
}

// ---------------- row softmax over fr_graph (rows of 512) ----------------
__global__ void softmax_rows(float* __restrict__ fr)
{
    const int t = threadIdx.x;                  // 128 threads, float4 per thread
    float* rowp = fr + (size_t)blockIdx.x * SEQ;
    __shared__ float sred[4];

    float4 v = reinterpret_cast<float4*>(rowp)[t];
    float mx = fmaxf(fmaxf(v.x, v.y), fmaxf(v.z, v.w));
#pragma unroll
    for (int o = 16; o; o >>= 1) mx = fmaxf(mx, __shfl_xor_sync(0xffffffffu, mx, o));
    if ((t & 31) == 0) sred[t >> 5] = mx;
    __syncthreads();
    mx = fmaxf(fmaxf(sred[0],sred[1]), fmaxf(sred[2],sred[3]));
    __syncthreads();

    v.x = expf(v.x - mx); v.y = expf(v.y - mx);
    v.z = expf(v.z - mx); v.w = expf(v.w - mx);
    float s = v.x + v.y + v.z + v.w;
#pragma unroll
    for (int o = 16; o; o >>= 1) s += __shfl_xor_sync(0xffffffffu, s, o);
    if ((t & 31) == 0) sred[t >> 5] = s;
    __syncthreads();
    s = sred[0]+sred[1]+sred[2]+sred[3];
    const float inv = 1.f/s;
    v.x *= inv; v.y *= inv; v.z *= inv; v.w *= inv;
    reinterpret_cast<float4*>(rowp)[t] = v;
}

// ---------------- generic tf32 tile GEMM: C = A[M,K] @ B[N,K]^T (+ epilogue) ----------------
// MODE 0: f_head proj   (A=x_q,  B=W_head) -> g_fhead, (acc+bias)*rel_emb
// MODE 1: f_tail proj   (A=x_kv, B=W_head) -> g_ftail, (acc+bias)*rel_emb
// MODE 2: f_v proj      (A=x_kv, B=W_v)    -> g_fvT (transposed), acc+bias
// MODE 3: scores        (A=g_fhead[z], B=g_ftail[z]) -> fr[z], acc/sqrt(dh)+adjm
// MODE 4: P @ V         (A=fr[z], B=g_fvT[z]) -> g_attn   [3xTF32 split]
// MODE 5: out proj      (A=g_attn, B=W_out) -> out_x, acc+bias   [3xTF32 split]
template<int MODE>
__device__ __forceinline__ void store_elem(float v, int m, int n, int z,
    const float* __restrict__ bias, const float* __restrict__ aux,
    float* __restrict__ Cext)
{
    if constexpr (MODE == 0 || MODE == 1) {
        v += bias[n];
        v *= aux[n];                                   // rel_emb flat [H*DH] == n
        const int b = m >> 9, q = m & 511, h = n >> 7, dh = n & 127;
        float* dst = (MODE == 0) ? g_fhead : g_ftail;
        dst[(((size_t)((b<<3)|h))*SEQ + q)*DHEAD + dh] = v;
    } else if constexpr (MODE == 2) {
        v += bias[n];
        const int b = m >> 9, q = m & 511, h = n >> 7, dh = n & 127;
        g_fvT[(((size_t)((b<<3)|h))*DHEAD + dh)*SEQ + q] = v;
    } else if constexpr (MODE == 3) {
        const int h = z & 7;
        const size_t off = (size_t)m*SEQ + n;
        Cext[(size_t)z*SEQ*SEQ + off] =
            v * 0.08838834764831845f + g_adjm[(size_t)h*SEQ*SEQ + off];
    } else if constexpr (MODE == 4) {
        const int b = z >> 3, h = z & 7;
        g_attn[((size_t)b*SEQ + m)*DMODEL + h*DHEAD + n] = v;
    } else {
        v += bias[n];
        Cext[(size_t)m*DMODEL + n] = v;
    }
}

template<int MODE>
__global__ void __launch_bounds__(256, 1)
gemm_tf32(const float* __restrict__ Aext, const float* __restrict__ Bext,
          const float* __restrict__ bias, const float* __restrict__ aux,
          float* __restrict__ Cext, int M, int N, int K)
{
    constexpr bool SPLIT = (MODE == 4 || MODE == 5);
    constexpr int BM = 128, BN = 128, BK = 16, BKP = 20;

    __shared__ float Ah[BM][BKP];
    __shared__ float Bh[BN][BKP];
    __shared__ float Al[SPLIT ? BM : 1][BKP];
    __shared__ float Bl[SPLIT ? BN : 1][BKP];

    const int tid  = threadIdx.x;
    const int lane = tid & 31;
    const int warp = tid >> 5;
    const int wm   = warp >> 2;   // 0..1  (64 rows each)
    const int wn   = warp & 3;    // 0..3  (32 cols each)
    const int z    = blockIdx.z;

    const float* A  = Aext;
    const float* Bp = Bext;
    if constexpr (MODE == 3) {
        A  = g_fhead + (size_t)z*SEQ*DHEAD;
        Bp = g_ftail + (size_t)z*SEQ*DHEAD;
    }
    if constexpr (MODE == 4) {
        A  = Aext + (size_t)z*SEQ*SEQ;
        Bp = g_fvT + (size_t)z*DHEAD*SEQ;
    }
    if constexpr (MODE == 5) {
        A  = g_attn;
    }

    const int m0 = blockIdx.y * BM;
    const int n0 = blockIdx.x * BN;

    float acc[4][4][4];
#pragma unroll
    for (int i = 0; i < 4; i++)
#pragma unroll
        for (int j = 0; j < 4; j++)
#pragma unroll
            for (int f = 0; f < 4; f++) acc[i][j][f] = 0.f;

    const int lrow = tid >> 2;          // 0..63
    const int lc4  = (tid & 3) << 2;    // 0,4,8,12

    for (int kt = 0; kt < K; kt += BK) {
#pragma unroll
        for (int i = 0; i < 2; i++) {
            const int r = lrow + i*64;
            float4 va = *reinterpret_cast<const float4*>(A  + (size_t)(m0 + r)*K + kt + lc4);
            float4 vb = *reinterpret_cast<const float4*>(Bp + (size_t)(n0 + r)*K + kt + lc4);
            unsigned ax = f2tf32(va.x), ay = f2tf32(va.y), az = f2tf32(va.z), aw = f2tf32(va.w);
            unsigned bx = f2tf32(vb.x), by = f2tf32(vb.y), bz = f2tf32(vb.z), bw = f2tf32(vb.w);
            Ah[r][lc4+0] = __uint_as_float(ax); Ah[r][lc4+1] = __uint_as_float(ay);
            Ah[r][lc4+2] = __uint_as_float(az); Ah[r][lc4+3] = __uint_as_float(aw);
            Bh[r][lc4+0] = __uint_as_float(bx); Bh[r][lc4+1] = __uint_as_float(by);
            Bh[r][lc4+2] = __uint_as_float(bz); Bh[r][lc4+3] = __uint_as_float(bw);
            if constexpr (SPLIT) {
                Al[r][lc4+0] = __uint_as_float(f2tf32(va.x - __uint_as_float(ax)));
                Al[r][lc4+1] = __uint_as_float(f2tf32(va.y - __uint_as_float(ay)));
                Al[r][lc4+2] = __uint_as_float(f2tf32(va.z - __uint_as_float(az)));
                Al[r][lc4+3] = __uint_as_float(f2tf32(va.w - __uint_as_float(aw)));
                Bl[r][lc4+0] = __uint_as_float(f2tf32(vb.x - __uint_as_float(bx)));
                Bl[r][lc4+1] = __uint_as_float(f2tf32(vb.y - __uint_as_float(by)));
                Bl[r][lc4+2] = __uint_as_float(f2tf32(vb.z - __uint_as_float(bz)));
                Bl[r][lc4+3] = __uint_as_float(f2tf32(vb.w - __uint_as_float(bw)));
            }
        }
        __syncthreads();

#pragma unroll
        for (int ks = 0; ks < 2; ks++) {
            const int kb = ks*8;
            const int lr = lane >> 2;
            const int lc = lane & 3;
            unsigned ah[4][4], bhf[4][2];
            unsigned alo[4][4], blo[4][2];
#pragma unroll
            for (int mt = 0; mt < 4; mt++) {
                const int r = wm*64 + mt*16 + lr;
                ah[mt][0] = __float_as_uint(Ah[r  ][kb+lc  ]);
                ah[mt][1] = __float_as_uint(Ah[r+8][kb+lc  ]);
                ah[mt][2] = __float_as_uint(Ah[r  ][kb+lc+4]);
                ah[mt][3] = __float_as_uint(Ah[r+8][kb+lc+4]);
                if constexpr (SPLIT) {
                    alo[mt][0] = __float_as_uint(Al[r  ][kb+lc  ]);
                    alo[mt][1] = __float_as_uint(Al[r+8][kb+lc  ]);
                    alo[mt][2] = __float_as_uint(Al[r  ][kb+lc+4]);
                    alo[mt][3] = __float_as_uint(Al[r+8][kb+lc+4]);
                }
            }
#pragma unroll
            for (int nt = 0; nt < 4; nt++) {
                const int c = wn*32 + nt*8 + lr;
                bhf[nt][0] = __float_as_uint(Bh[c][kb+lc  ]);
                bhf[nt][1] = __float_as_uint(Bh[c][kb+lc+4]);
                if constexpr (SPLIT) {
                    blo[nt][0] = __float_as_uint(Bl[c][kb+lc  ]);
                    blo[nt][1] = __float_as_uint(Bl[c][kb+lc+4]);
                }
            }
#pragma unroll
            for (int mt = 0; mt < 4; mt++)
#pragma unroll
                for (int nt = 0; nt < 4; nt++) {
                    mma8(acc[mt][nt], ah[mt], bhf[nt]);
                    if constexpr (SPLIT) {
                        mma8(acc[mt][nt], alo[mt], bhf[nt]);
                        mma8(acc[mt][nt], ah[mt],  blo[nt]);
                    }
                }
        }
        __syncthreads();
    }

    // epilogue
    const int lr  = lane >> 2;
    const int lc2 = (lane & 3) << 1;
#pragma unroll
    for (int mt = 0; mt < 4; mt++)
#pragma unroll
        for (int nt = 0; nt < 4; nt++) {
            const int mb = m0 + wm*64 + mt*16 + lr;
            const int nb = n0 + wn*32 + nt*8 + lc2;
            store_elem<MODE>(acc[mt][nt][0], mb,   nb,   z, bias, aux, Cext);
            store_elem<MODE>(acc[mt][nt][1], mb,   nb+1, z, bias, aux, Cext);
            store_elem<MODE>(acc[mt][nt][2], mb+8, nb,   z, bias, aux, Cext);
            store_elem<MODE>(acc[mt][nt][3], mb+8, nb+1, z, bias, aux, Cext);
        }
}

// ---------------- launch ----------------
extern "C" void kernel_launch(void* const* d_in, const int* in_sizes, int n_in,
                              void* d_out, int out_size)
{
    const float* x_q      = (const float*)d_in[0];
    const float* x_kv     = (const float*)d_in[1];
    const float* W_head_w = (const float*)d_in[2];
    const float* W_head_b = (const float*)d_in[3];
    const float* W_v_w    = (const float*)d_in[4];
    const float* W_v_b    = (const float*)d_in[5];
    const float* W_out_w  = (const float*)d_in[6];
    const float* W_out_b  = (const float*)d_in[7];
    const float* rel_emb  = (const float*)d_in[8];
    const float* col_head = (const float*)d_in[9];
    const float* col_tail = (const float*)d_in[10];

    float* out_x  = (float*)d_out;                          // [32,512,1024]
    float* out_fr = out_x + (size_t)BATCH*SEQ*DMODEL;       // [256,512,512]

    // 1) learned column topology mask
    adj_kernel<<<dim3(SEQ, HEADS), 128>>>(col_head, col_tail);

    // 2) projections
    gemm_tf32<0><<<dim3(8, 128), 256>>>(x_q,  W_head_w, W_head_b, rel_emb, nullptr,
                                        BATCH*SEQ, DMODEL, DMODEL);
    gemm_tf32<1><<<dim3(8, 128), 256>>>(x_kv, W_head_w, W_head_b, rel_emb, nullptr,
                                        BATCH*SEQ, DMODEL, DMODEL);
    gemm_tf32<2><<<dim3(8, 128), 256>>>(x_kv, W_v_w,    W_v_b,    nullptr, nullptr,
                                        BATCH*SEQ, DMODEL, DMODEL);

    // 3) scores + mask  -> fr region of d_out (raw logits)
    gemm_tf32<3><<<dim3(4, 4, BHS), 256>>>(nullptr, nullptr, nullptr, nullptr, out_fr,
                                           SEQ, SEQ, DHEAD);

    // 4) softmax rows in place
    softmax_rows<<<BHS*SEQ, 128>>>(out_fr);

    // 5) attention output = P @ V  (split tf32)
    gemm_tf32<4><<<dim3(1, 4, BHS), 256>>>(out_fr, nullptr, nullptr, nullptr, nullptr,
                                           SEQ, DHEAD, SEQ);

    // 6) output projection (split tf32)
    gemm_tf32<5><<<dim3(8, 128), 256>>>(nullptr, W_out_w, W_out_b, nullptr, out_x,
                                        BATCH*SEQ, DMODEL, DMODEL);
}

// round 2
// speedup vs baseline: 1.5919x; 1.5919x over previous
#include <cuda_runtime.h>
#include <math.h>

#define BATCH   32
#define HEADS   8
#define SEQ     512
#define DMODEL  1024
#define DHEAD   128
#define DCOL    18
#define BHS     (BATCH*HEADS)   // 256

// ---------------- scratch (static device globals; no allocation) ----------------
__device__ __align__(256) float g_fhead[(size_t)BHS*SEQ*DHEAD];   // [b,h,q,dh]
__device__ __align__(256) float g_ftail[(size_t)BHS*SEQ*DHEAD];   // [b,h,k,dh]
__device__ __align__(256) float g_fv   [(size_t)BHS*SEQ*DHEAD];   // [b,h,k,dh]  (natural layout)
__device__ __align__(256) float g_adjm [(size_t)HEADS*SEQ*SEQ];   // (1-adj)*(-10000)
__device__ __align__(256) float g_attn [(size_t)BATCH*SEQ*DMODEL];// [b,q,h*dh]

// ---------------- helpers ----------------
__device__ __forceinline__ unsigned f2tf32(float f) {
    unsigned u;
    asm("cvt.rna.tf32.f32 %0, %1;" : "=r"(u) : "f"(f));
    return u;
}

__device__ __forceinline__ void mma8(float* c, const unsigned* a, const unsigned* b) {
    asm volatile(
        "mma.sync.aligned.m16n8k8.row.col.f32.tf32.tf32.f32 "
        "{%0,%1,%2,%3}, {%4,%5,%6,%7}, {%8,%9}, {%0,%1,%2,%3};\n"
        : "+f"(c[0]), "+f"(c[1]), "+f"(c[2]), "+f"(c[3])
        : "r"(a[0]), "r"(a[1]), "r"(a[2]), "r"(a[3]), "r"(b[0]), "r"(b[1]));
}

__device__ __forceinline__ void cpa16(void* dst, const void* src) {
    unsigned d = (unsigned)__cvta_generic_to_shared(dst);
    asm volatile("cp.async.ca.shared.global [%0], [%1], 16;" :: "r"(d), "l"(src));
}
__device__ __forceinline__ void cpa_commit() { asm volatile("cp.async.commit_group;"); }
template<int N>
__device__ __forceinline__ void cpa_wait() { asm volatile("cp.async.wait_group %0;" :: "n"(N)); }

// ---------------- adjacency: softmax(col_head @ col_tail^T, diag=0) ----------------
__global__ void adj_kernel(const float* __restrict__ col_head,
                           const float* __restrict__ col_tail)
{
    const int q = blockIdx.x;
    const int h = blockIdx.y;
    const int t = threadIdx.x;                 // 128 threads
    __shared__ float ch[DCOL];
    __shared__ float sred[4];

    if (t < DCOL) ch[t] = col_head[((size_t)h*SEQ + q)*DCOL + t];
    __syncthreads();

    float l[4];
#pragma unroll
    for (int i = 0; i < 4; i++) {
        const int k = t + i*128;
        const float* ct = col_tail + ((size_t)h*SEQ + k)*DCOL;
        float s = 0.f;
#pragma unroll
        for (int c = 0; c < DCOL; c++) s += ch[c]*ct[c];
        l[i] = (k == q) ? 0.f : s;             // zero diagonal BEFORE softmax
    }

    float mx = fmaxf(fmaxf(l[0],l[1]), fmaxf(l[2],l[3]));
#pragma unroll
    for (int o = 16; o; o >>= 1) mx = fmaxf(mx, __shfl_xor_sync(0xffffffffu, mx, o));
    if ((t & 31) == 0) sred[t >> 5] = mx;
    __syncthreads();
    mx = fmaxf(fmaxf(sred[0],sred[1]), fmaxf(sred[2],sred[3]));
    __syncthreads();

    float e[4]; float sum = 0.f;
#pragma unroll
    for (int i = 0; i < 4; i++) { e[i] = expf(l[i]-mx); sum += e[i]; }
#pragma unroll
    for (int o = 16; o; o >>= 1) sum += __shfl_xor_sync(0xffffffffu, sum, o);
    if ((t & 31) == 0) sred[t >> 5] = sum;
    __syncthreads();
    sum = sred[0]+sred[1]+sred[2]+sred[3];
    const float inv = 1.f/sum;

    float* dst = g_adjm + ((size_t)h*SEQ + q)*SEQ;
#pragma unroll
    for (int i = 0; i < 4; i++) {
        const int k = t + i*128;
        dst[k] = (1.f - e[i]*inv) * (-10000.f);
    }
}

// ---------------- row softmax over fr_graph (rows of 512) ----------------
__global__ void softmax_rows(float* __restrict__ fr)
{
    const int t = threadIdx.x;                  // 128 threads, float4 per thread
    float* rowp = fr + (size_t)blockIdx.x * SEQ;
    __shared__ float sred[4];

    float4 v = reinterpret_cast<float4*>(rowp)[t];
    float mx = fmaxf(fmaxf(v.x, v.y), fmaxf(v.z, v.w));
#pragma unroll
    for (int o = 16; o; o >>= 1) mx = fmaxf(mx, __shfl_xor_sync(0xffffffffu, mx, o));
    if ((t & 31) == 0) sred[t >> 5] = mx;
    __syncthreads();
    mx = fmaxf(fmaxf(sred[0],sred[1]), fmaxf(sred[2],sred[3]));
    __syncthreads();

    v.x = expf(v.x - mx); v.y = expf(v.y - mx);
    v.z = expf(v.z - mx); v.w = expf(v.w - mx);
    float s = v.x + v.y + v.z + v.w;
#pragma unroll
    for (int o = 16; o; o >>= 1) s += __shfl_xor_sync(0xffffffffu, s, o);
    if ((t & 31) == 0) sred[t >> 5] = s;
    __syncthreads();
    s = sred[0]+sred[1]+sred[2]+sred[3];
    const float inv = 1.f/s;
    v.x *= inv; v.y *= inv; v.z *= inv; v.w *= inv;
    reinterpret_cast<float4*>(rowp)[t] = v;
}

// ---------------- mode-specific epilogue: stores a contiguous (n, n+1) pair ----------------
// MODE 0: f_head proj -> g_fhead, (acc+bias)*rel_emb
// MODE 1: f_tail proj -> g_ftail, (acc+bias)*rel_emb
// MODE 2: f_v proj    -> g_fv (natural), acc+bias
// MODE 3: scores      -> fr[z], acc/sqrt(dh)+adjm
// MODE 4: P @ V       -> g_attn                [3xTF32 split]
// MODE 5: out proj    -> out_x, acc+bias       [3xTF32 split]
template<int MODE>
__device__ __forceinline__ void store_pair(float v0, float v1, int m, int n, int z,
    const float* __restrict__ bias, const float* __restrict__ aux,
    float* __restrict__ Cext)
{
    float2 o;
    if constexpr (MODE == 0 || MODE == 1 || MODE == 2) {
        v0 += bias[n];   v1 += bias[n+1];
        if constexpr (MODE != 2) { v0 *= aux[n]; v1 *= aux[n+1]; }
        const int b = m >> 9, q = m & 511, h = n >> 7, dh = n & 127;
        float* dst = (MODE == 0) ? g_fhead : (MODE == 1) ? g_ftail : g_fv;
        o.x = v0; o.y = v1;
        *reinterpret_cast<float2*>(&dst[(((size_t)((b<<3)|h))*SEQ + q)*DHEAD + dh]) = o;
    } else if constexpr (MODE == 3) {
        const int h = z & 7;
        const size_t off = (size_t)m*SEQ + n;
        float2 am = *reinterpret_cast<const float2*>(&g_adjm[(size_t)h*SEQ*SEQ + off]);
        o.x = v0 * 0.08838834764831845f + am.x;
        o.y = v1 * 0.08838834764831845f + am.y;
        *reinterpret_cast<float2*>(&Cext[(size_t)z*SEQ*SEQ + off]) = o;
    } else if constexpr (MODE == 4) {
        const int b = z >> 3, h = z & 7;
        o.x = v0; o.y = v1;
        *reinterpret_cast<float2*>(&g_attn[((size_t)b*SEQ + m)*DMODEL + h*DHEAD + n]) = o;
    } else {
        o.x = v0 + bias[n]; o.y = v1 + bias[n+1];
        *reinterpret_cast<float2*>(&Cext[(size_t)m*DMODEL + n]) = o;
    }
}

// ---------------- pipelined tf32 tile GEMM: C = A[M,K] @ B[N,K]^T ----------------
// MODE 4 stores B in smem as [BK][BN] ([k][n], coalesced from natural V layout).
template<int MODE>
__global__ void __launch_bounds__(256, ((MODE==4)||(MODE==5)) ? 1 : 2)
gemm_tf32(const float* __restrict__ Aext, const float* __restrict__ Bext,
          const float* __restrict__ bias, const float* __restrict__ aux,
          float* __restrict__ Cext, int M, int N, int K)
{
    constexpr bool SPLIT = (MODE == 4 || MODE == 5);
    constexpr bool BKN   = (MODE == 4);       // B smem layout [k][n]
    constexpr int BM = 128, BN = 128, BK = 16;
    constexpr int BROWS = BKN ? BK : BN;
    constexpr int BCOLS = BKN ? 132 : 20;

    __shared__ __align__(16) float As[2][BM][20];
    __shared__ __align__(16) float Bs[2][BROWS][BCOLS];

    const int tid  = threadIdx.x;
    const int lane = tid & 31;
    const int warp = tid >> 5;
    const int wm   = warp >> 2;   // 0..1  (64 rows each)
    const int wn   = warp & 3;    // 0..3  (32 cols each)
    const int z    = blockIdx.z;

    const float* A  = Aext;
    const float* Bp = Bext;
    if constexpr (MODE == 3) {
        A  = g_fhead + (size_t)z*SEQ*DHEAD;
        Bp = g_ftail + (size_t)z*SEQ*DHEAD;
    }
    if constexpr (MODE == 4) {
        A  = Aext + (size_t)z*SEQ*SEQ;
        Bp = g_fv + (size_t)z*SEQ*DHEAD;
    }
    if constexpr (MODE == 5) {
        A  = g_attn;
    }

    const int m0 = blockIdx.y * BM;
    const int n0 = blockIdx.x * BN;

    // ---- async loaders ----
    const int lrow = tid >> 2;          // 0..63
    const int lc4  = (tid & 3) << 2;    // 0,4,8,12

    auto load_stage = [&](int st, int kt) {
        // A tile: 128 x 16
        cpa16(&As[st][lrow     ][lc4], A + (size_t)(m0 + lrow     )*K + kt + lc4);
        cpa16(&As[st][lrow + 64][lc4], A + (size_t)(m0 + lrow + 64)*K + kt + lc4);
        if constexpr (BKN) {
            // B tile: 16 rows (k) x 128 cols (n), contiguous rows in gmem
#pragma unroll
            for (int i = 0; i < 2; i++) {
                const int idx = tid + i*256;          // 0..511 float4 slots
                const int kr  = idx >> 5;             // 0..15
                const int c4  = (idx & 31) << 2;      // 0..124
                cpa16(&Bs[st][kr][c4], Bp + (size_t)(kt + kr)*DHEAD + c4);
            }
        } else {
            cpa16(&Bs[st][lrow     ][lc4], Bp + (size_t)(n0 + lrow     )*K + kt + lc4);
            cpa16(&Bs[st][lrow + 64][lc4], Bp + (size_t)(n0 + lrow + 64)*K + kt + lc4);
        }
    };

    float acc[4][4][4];
#pragma unroll
    for (int i = 0; i < 4; i++)
#pragma unroll
        for (int j = 0; j < 4; j++)
#pragma unroll
            for (int f = 0; f < 4; f++) acc[i][j][f] = 0.f;

    const int iters = K / BK;
    load_stage(0, 0);
    cpa_commit();

    const int lr = lane >> 2;
    const int lc = lane & 3;

    for (int it = 0; it < iters; ++it) {
        const int cur = it & 1;
        if (it + 1 < iters) {
            load_stage(cur ^ 1, (it + 1) * BK);
            cpa_commit();
            cpa_wait<1>();
        } else {
            cpa_wait<0>();
        }
        __syncthreads();

#pragma unroll
        for (int ks = 0; ks < 2; ks++) {
            const int kb = ks * 8;
            unsigned ah[4][4], bhf[4][2];
            unsigned alo[4][4], blo[4][2];
#pragma unroll
            for (int mt = 0; mt < 4; mt++) {
                const int r = wm*64 + mt*16 + lr;
                float f0 = As[cur][r  ][kb+lc  ];
                float f1 = As[cur][r+8][kb+lc  ];
                float f2 = As[cur][r  ][kb+lc+4];
                float f3 = As[cur][r+8][kb+lc+4];
                ah[mt][0] = f2tf32(f0); ah[mt][1] = f2tf32(f1);
                ah[mt][2] = f2tf32(f2); ah[mt][3] = f2tf32(f3);
                if constexpr (SPLIT) {
                    alo[mt][0] = f2tf32(f0 - __uint_as_float(ah[mt][0]));
                    alo[mt][1] = f2tf32(f1 - __uint_as_float(ah[mt][1]));
                    alo[mt][2] = f2tf32(f2 - __uint_as_float(ah[mt][2]));
                    alo[mt][3] = f2tf32(f3 - __uint_as_float(ah[mt][3]));
                }
            }
#pragma unroll
            for (int nt = 0; nt < 4; nt++) {
                const int c = wn*32 + nt*8 + lr;
                float f0, f1;
                if constexpr (BKN) {
                    f0 = Bs[cur][kb+lc  ][c];
                    f1 = Bs[cur][kb+lc+4][c];
                } else {
                    f0 = Bs[cur][c][kb+lc  ];
                    f1 = Bs[cur][c][kb+lc+4];
                }
                bhf[nt][0] = f2tf32(f0); bhf[nt][1] = f2tf32(f1);
                if constexpr (SPLIT) {
                    blo[nt][0] = f2tf32(f0 - __uint_as_float(bhf[nt][0]));
                    blo[nt][1] = f2tf32(f1 - __uint_as_float(bhf[nt][1]));
                }
            }
#pragma unroll
            for (int mt = 0; mt < 4; mt++)
#pragma unroll
                for (int nt = 0; nt < 4; nt++) {
                    mma8(acc[mt][nt], ah[mt], bhf[nt]);
                    if constexpr (SPLIT) {
                        mma8(acc[mt][nt], alo[mt], bhf[nt]);
                        mma8(acc[mt][nt], ah[mt],  blo[nt]);
                    }
                }
        }
        __syncthreads();
    }

    // epilogue: each acc quad holds (m,n),(m,n+1),(m+8,n),(m+8,n+1)
    const int lr2 = lane >> 2;
    const int lc2 = (lane & 3) << 1;
#pragma unroll
    for (int mt = 0; mt < 4; mt++)
#pragma unroll
        for (int nt = 0; nt < 4; nt++) {
            const int mb = m0 + wm*64 + mt*16 + lr2;
            const int nb = n0 + wn*32 + nt*8 + lc2;
            store_pair<MODE>(acc[mt][nt][0], acc[mt][nt][1], mb,   nb, z, bias, aux, Cext);
            store_pair<MODE>(acc[mt][nt][2], acc[mt][nt][3], mb+8, nb, z, bias, aux, Cext);
        }
}

// ---------------- launch ----------------
extern "C" void kernel_launch(void* const* d_in, const int* in_sizes, int n_in,
                              void* d_out, int out_size)
{
    const float* x_q      = (const float*)d_in[0];
    const float* x_kv     = (const float*)d_in[1];
    const float* W_head_w = (const float*)d_in[2];
    const float* W_head_b = (const float*)d_in[3];
    const float* W_v_w    = (const float*)d_in[4];
    const float* W_v_b    = (const float*)d_in[5];
    const float* W_out_w  = (const float*)d_in[6];
    const float* W_out_b  = (const float*)d_in[7];
    const float* rel_emb  = (const float*)d_in[8];
    const float* col_head = (const float*)d_in[9];
    const float* col_tail = (const float*)d_in[10];

    float* out_x  = (float*)d_out;                          // [32,512,1024]
    float* out_fr = out_x + (size_t)BATCH*SEQ*DMODEL;       // [256,512,512]

    // 1) learned column topology mask
    adj_kernel<<<dim3(SEQ, HEADS), 128>>>(col_head, col_tail);

    // 2) projections
    gemm_tf32<0><<<dim3(8, 128), 256>>>(x_q,  W_head_w, W_head_b, rel_emb, nullptr,
                                        BATCH*SEQ, DMODEL, DMODEL);
    gemm_tf32<1><<<dim3(8, 128), 256>>>(x_kv, W_head_w, W_head_b, rel_emb, nullptr,
                                        BATCH*SEQ, DMODEL, DMODEL);
    gemm_tf32<2><<<dim3(8, 128), 256>>>(x_kv, W_v_w,    W_v_b,    nullptr, nullptr,
                                        BATCH*SEQ, DMODEL, DMODEL);

    // 3) scores + mask  -> fr region of d_out (raw logits)
    gemm_tf32<3><<<dim3(4, 4, BHS), 256>>>(nullptr, nullptr, nullptr, nullptr, out_fr,
                                           SEQ, SEQ, DHEAD);

    // 4) softmax rows in place
    softmax_rows<<<BHS*SEQ, 128>>>(out_fr);

    // 5) attention output = P @ V  (split tf32)
    gemm_tf32<4><<<dim3(1, 4, BHS), 256>>>(out_fr, nullptr, nullptr, nullptr, nullptr,
                                           SEQ, DHEAD, SEQ);

    // 6) output projection (split tf32)
    gemm_tf32<5><<<dim3(8, 128), 256>>>(nullptr, W_out_w, W_out_b, nullptr, out_x,
                                        BATCH*SEQ, DMODEL, DMODEL);
}

// round 3
// speedup vs baseline: 1.6469x; 1.0346x over previous
#include <cuda_runtime.h>
#include <math.h>

#define BATCH   32
#define HEADS   8
#define SEQ     512
#define DMODEL  1024
#define DHEAD   128
#define DCOL    18
#define BHS     (BATCH*HEADS)   // 256

// ---------------- scratch (static device globals; no allocation) ----------------
__device__ __align__(256) float g_fhead[(size_t)BHS*SEQ*DHEAD];   // [b,h,q,dh]
__device__ __align__(256) float g_ftail[(size_t)BHS*SEQ*DHEAD];   // [b,h,k,dh]
__device__ __align__(256) float g_fv   [(size_t)BHS*SEQ*DHEAD];   // [b,h,k,dh]
__device__ __align__(256) float g_adjm [(size_t)HEADS*SEQ*SEQ];   // (1-adj)*(-10000)
__device__ __align__(256) float g_attn [(size_t)BATCH*SEQ*DMODEL];// [b,q,h*dh]

// ---------------- helpers ----------------
__device__ __forceinline__ unsigned f2tf32(float f) {
    unsigned u;
    asm("cvt.rna.tf32.f32 %0, %1;" : "=r"(u) : "f"(f));
    return u;
}

__device__ __forceinline__ void mma8(float* c, const unsigned* a, const unsigned* b) {
    asm volatile(
        "mma.sync.aligned.m16n8k8.row.col.f32.tf32.tf32.f32 "
        "{%0,%1,%2,%3}, {%4,%5,%6,%7}, {%8,%9}, {%0,%1,%2,%3};\n"
        : "+f"(c[0]), "+f"(c[1]), "+f"(c[2]), "+f"(c[3])
        : "r"(a[0]), "r"(a[1]), "r"(a[2]), "r"(a[3]), "r"(b[0]), "r"(b[1]));
}

__device__ __forceinline__ void mmabf(float* c, unsigned a0, unsigned a1, unsigned a2,
                                      unsigned a3, unsigned b0, unsigned b1) {
    asm volatile(
        "mma.sync.aligned.m16n8k16.row.col.f32.bf16.bf16.f32 "
        "{%0,%1,%2,%3}, {%4,%5,%6,%7}, {%8,%9}, {%0,%1,%2,%3};\n"
        : "+f"(c[0]), "+f"(c[1]), "+f"(c[2]), "+f"(c[3])
        : "r"(a0), "r"(a1), "r"(a2), "r"(a3), "r"(b0), "r"(b1));
}

__device__ __forceinline__ void cpa16(void* dst, const void* src) {
    unsigned d = (unsigned)__cvta_generic_to_shared(dst);
    asm volatile("cp.async.ca.shared.global [%0], [%1], 16;" :: "r"(d), "l"(src));
}
__device__ __forceinline__ void cpa_commit() { asm volatile("cp.async.commit_group;"); }
template<int N>
__device__ __forceinline__ void cpa_wait() { asm volatile("cp.async.wait_group %0;" :: "n"(N)); }

// pack two floats to bf16x2: f0 -> lower (even k), f1 -> upper (odd k)
__device__ __forceinline__ unsigned packbf(float f0, float f1) {
    unsigned d;
    asm("cvt.rn.bf16x2.f32 %0, %1, %2;" : "=r"(d) : "f"(f1), "f"(f0));
    return d;
}
__device__ __forceinline__ float bf_lo(unsigned p) { return __uint_as_float(p << 16); }
__device__ __forceinline__ float bf_up(unsigned p) { return __uint_as_float(p & 0xFFFF0000u); }

// 8 consecutive-k floats -> 4 hi packs + 4 lo packs (natural unit order)
__device__ __forceinline__ void cvt8(const float* f, unsigned* ph, unsigned* pl) {
#pragma unroll
    for (int j = 0; j < 4; j++) {
        unsigned h = packbf(f[2*j], f[2*j+1]);
        ph[j] = h;
        pl[j] = packbf(f[2*j] - bf_lo(h), f[2*j+1] - bf_up(h));
    }
}

// ---------------- adjacency: softmax(col_head @ col_tail^T, diag=0) ----------------
__global__ void adj_kernel(const float* __restrict__ col_head,
                           const float* __restrict__ col_tail)
{
    const int q = blockIdx.x;
    const int h = blockIdx.y;
    const int t = threadIdx.x;                 // 128 threads
    __shared__ float ch[DCOL];
    __shared__ float sred[4];

    if (t < DCOL) ch[t] = col_head[((size_t)h*SEQ + q)*DCOL + t];
    __syncthreads();

    float l[4];
#pragma unroll
    for (int i = 0; i < 4; i++) {
        const int k = t + i*128;
        const float* ct = col_tail + ((size_t)h*SEQ + k)*DCOL;
        float s = 0.f;
#pragma unroll
        for (int c = 0; c < DCOL; c++) s += ch[c]*ct[c];
        l[i] = (k == q) ? 0.f : s;             // zero diagonal BEFORE softmax
    }

    float mx = fmaxf(fmaxf(l[0],l[1]), fmaxf(l[2],l[3]));
#pragma unroll
    for (int o = 16; o; o >>= 1) mx = fmaxf(mx, __shfl_xor_sync(0xffffffffu, mx, o));
    if ((t & 31) == 0) sred[t >> 5] = mx;
    __syncthreads();
    mx = fmaxf(fmaxf(sred[0],sred[1]), fmaxf(sred[2],sred[3]));
    __syncthreads();

    float e[4]; float sum = 0.f;
#pragma unroll
    for (int i = 0; i < 4; i++) { e[i] = expf(l[i]-mx); sum += e[i]; }
#pragma unroll
    for (int o = 16; o; o >>= 1) sum += __shfl_xor_sync(0xffffffffu, sum, o);
    if ((t & 31) == 0) sred[t >> 5] = sum;
    __syncthreads();
    sum = sred[0]+sred[1]+sred[2]+sred[3];
    const float inv = 1.f/sum;

    float* dst = g_adjm + ((size_t)h*SEQ + q)*SEQ;
#pragma unroll
    for (int i = 0; i < 4; i++) {
        const int k = t + i*128;
        dst[k] = (1.f - e[i]*inv) * (-10000.f);
    }
}

// ---------------- row softmax over fr_graph (rows of 512) ----------------
__global__ void softmax_rows(float* __restrict__ fr)
{
    const int t = threadIdx.x;                  // 128 threads, float4 per thread
    float* rowp = fr + (size_t)blockIdx.x * SEQ;
    __shared__ float sred[4];

    float4 v = reinterpret_cast<float4*>(rowp)[t];
    float mx = fmaxf(fmaxf(v.x, v.y), fmaxf(v.z, v.w));
#pragma unroll
    for (int o = 16; o; o >>= 1) mx = fmaxf(mx, __shfl_xor_sync(0xffffffffu, mx, o));
    if ((t & 31) == 0) sred[t >> 5] = mx;
    __syncthreads();
    mx = fmaxf(fmaxf(sred[0],sred[1]), fmaxf(sred[2],sred[3]));
    __syncthreads();

    v.x = expf(v.x - mx); v.y = expf(v.y - mx);
    v.z = expf(v.z - mx); v.w = expf(v.w - mx);
    float s = v.x + v.y + v.z + v.w;
#pragma unroll
    for (int o = 16; o; o >>= 1) s += __shfl_xor_sync(0xffffffffu, s, o);
    if ((t & 31) == 0) sred[t >> 5] = s;
    __syncthreads();
    s = sred[0]+sred[1]+sred[2]+sred[3];
    const float inv = 1.f/s;
    v.x *= inv; v.y *= inv; v.z *= inv; v.w *= inv;
    reinterpret_cast<float4*>(rowp)[t] = v;
}

// ---------------- mode-specific epilogue: stores a contiguous (n, n+1) pair ----------------
template<int MODE>
__device__ __forceinline__ void store_pair(float v0, float v1, int m, int n, int z,
    const float* __restrict__ bias, const float* __restrict__ aux,
    float* __restrict__ Cext)
{
    float2 o;
    if constexpr (MODE == 0 || MODE == 1 || MODE == 2) {
        v0 += bias[n];   v1 += bias[n+1];
        if constexpr (MODE != 2) { v0 *= aux[n]; v1 *= aux[n+1]; }
        const int b = m >> 9, q = m & 511, h = n >> 7, dh = n & 127;
        float* dst = (MODE == 0) ? g_fhead : (MODE == 1) ? g_ftail : g_fv;
        o.x = v0; o.y = v1;
        *reinterpret_cast<float2*>(&dst[(((size_t)((b<<3)|h))*SEQ + q)*DHEAD + dh]) = o;
    } else if constexpr (MODE == 3) {
        const int h = z & 7;
        const size_t off = (size_t)m*SEQ + n;
        float2 am = *reinterpret_cast<const float2*>(&g_adjm[(size_t)h*SEQ*SEQ + off]);
        o.x = v0 * 0.08838834764831845f + am.x;
        o.y = v1 * 0.08838834764831845f + am.y;
        *reinterpret_cast<float2*>(&Cext[(size_t)z*SEQ*SEQ + off]) = o;
    } else if constexpr (MODE == 4) {
        const int b = z >> 3, h = z & 7;
        o.x = v0; o.y = v1;
        *reinterpret_cast<float2*>(&g_attn[((size_t)b*SEQ + m)*DMODEL + h*DHEAD + n]) = o;
    } else {
        o.x = v0 + bias[n]; o.y = v1 + bias[n+1];
        *reinterpret_cast<float2*>(&Cext[(size_t)m*DMODEL + n]) = o;
    }
}

// ---------------- pipelined tf32 tile GEMM (modes 0..3): C = A[M,K] @ B[N,K]^T ----------------
template<int MODE>
__global__ void __launch_bounds__(256, 2)
gemm_tf32(const float* __restrict__ Aext, const float* __restrict__ Bext,
          const float* __restrict__ bias, const float* __restrict__ aux,
          float* __restrict__ Cext, int M, int N, int K)
{
    constexpr int BM = 128, BN = 128, BK = 16;

    __shared__ __align__(16) float As[2][BM][20];
    __shared__ __align__(16) float Bs[2][BN][20];

    const int tid  = threadIdx.x;
    const int lane = tid & 31;
    const int warp = tid >> 5;
    const int wm   = warp >> 2;   // 0..1
    const int wn   = warp & 3;    // 0..3
    const int z    = blockIdx.z;

    const float* A  = Aext;
    const float* Bp = Bext;
    if constexpr (MODE == 3) {
        A  = g_fhead + (size_t)z*SEQ*DHEAD;
        Bp = g_ftail + (size_t)z*SEQ*DHEAD;
    }

    const int m0 = blockIdx.y * BM;
    const int n0 = blockIdx.x * BN;

    const int lrow = tid >> 2;          // 0..63
    const int lc4  = (tid & 3) << 2;    // 0,4,8,12

    auto load_stage = [&](int st, int kt) {
        cpa16(&As[st][lrow     ][lc4], A  + (size_t)(m0 + lrow     )*K + kt + lc4);
        cpa16(&As[st][lrow + 64][lc4], A  + (size_t)(m0 + lrow + 64)*K + kt + lc4);
        cpa16(&Bs[st][lrow     ][lc4], Bp + (size_t)(n0 + lrow     )*K + kt + lc4);
        cpa16(&Bs[st][lrow + 64][lc4], Bp + (size_t)(n0 + lrow + 64)*K + kt + lc4);
    };

    float acc[4][4][4];
#pragma unroll
    for (int i = 0; i < 4; i++)
#pragma unroll
        for (int j = 0; j < 4; j++)
#pragma unroll
            for (int f = 0; f < 4; f++) acc[i][j][f] = 0.f;

    const int iters = K / BK;
    load_stage(0, 0);
    cpa_commit();

    const int lr = lane >> 2;
    const int lc = lane & 3;

    for (int it = 0; it < iters; ++it) {
        const int cur = it & 1;
        if (it + 1 < iters) {
            load_stage(cur ^ 1, (it + 1) * BK);
            cpa_commit();
            cpa_wait<1>();
        } else {
            cpa_wait<0>();
        }
        __syncthreads();

#pragma unroll
        for (int ks = 0; ks < 2; ks++) {
            const int kb = ks * 8;
            unsigned ah[4][4], bhf[4][2];
            // logical-k permutation: memory pair (2lc,2lc+1) == logical (lc, lc+4)
#pragma unroll
            for (int mt = 0; mt < 4; mt++) {
                const int r = wm*64 + mt*16 + lr;
                float2 f01 = *reinterpret_cast<const float2*>(&As[cur][r  ][kb + 2*lc]);
                float2 f23 = *reinterpret_cast<const float2*>(&As[cur][r+8][kb + 2*lc]);
                ah[mt][0] = f2tf32(f01.x); ah[mt][1] = f2tf32(f23.x);
                ah[mt][2] = f2tf32(f01.y); ah[mt][3] = f2tf32(f23.y);
            }
#pragma unroll
            for (int nt = 0; nt < 4; nt++) {
                const int c = wn*32 + nt*8 + lr;
                float2 fb = *reinterpret_cast<const float2*>(&Bs[cur][c][kb + 2*lc]);
                bhf[nt][0] = f2tf32(fb.x); bhf[nt][1] = f2tf32(fb.y);
            }
#pragma unroll
            for (int mt = 0; mt < 4; mt++)
#pragma unroll
                for (int nt = 0; nt < 4; nt++)
                    mma8(acc[mt][nt], ah[mt], bhf[nt]);
        }
        __syncthreads();
    }

    const int lr2 = lane >> 2;
    const int lc2 = (lane & 3) << 1;
#pragma unroll
    for (int mt = 0; mt < 4; mt++)
#pragma unroll
        for (int nt = 0; nt < 4; nt++) {
            const int mb = m0 + wm*64 + mt*16 + lr2;
            const int nb = n0 + wn*32 + nt*8 + lc2;
            store_pair<MODE>(acc[mt][nt][0], acc[mt][nt][1], mb,   nb, z, bias, aux, Cext);
            store_pair<MODE>(acc[mt][nt][2], acc[mt][nt][3], mb+8, nb, z, bias, aux, Cext);
        }
}

// ---------------- bf16 3-split GEMM (modes 4,5): C = A[M,K] @ B[N,K]^T ----------------
// Producer: LDG fp32 -> regs -> hi/lo bf16x2 packs -> STS.128 into packed smem.
// Inner loop: LDS.64 fragment loads + 48 bf16 k16 mma per BK=16 (hi*hi + hi*lo + lo*hi).
template<int MODE>   // 4: P@V  (A=fr[z], B=g_fv[z] [k][dh]) ; 5: out proj (A=g_attn, B=W_out)
__global__ void __launch_bounds__(256, 2)
gemm_split(const float* __restrict__ Aext, const float* __restrict__ Bext,
           const float* __restrict__ bias, float* __restrict__ Cext, int K)
{
    constexpr int BM = 128, BN = 128, BK = 16, PPAD = 12;
    __shared__ __align__(16) unsigned pAh[BM][PPAD];
    __shared__ __align__(16) unsigned pAl[BM][PPAD];
    __shared__ __align__(16) unsigned pBh[BN][PPAD];
    __shared__ __align__(16) unsigned pBl[BN][PPAD];

    const int tid  = threadIdx.x;
    const int lane = tid & 31;
    const int warp = tid >> 5;
    const int wm   = warp >> 2, wn = warp & 3;
    const int lr   = lane >> 2, lc = lane & 3;
    const int z    = blockIdx.z;

    const float* A; const float* Bp;
    if constexpr (MODE == 4) { A = Aext + (size_t)z*SEQ*SEQ;  Bp = g_fv + (size_t)z*SEQ*DHEAD; }
    else                     { A = g_attn;                    Bp = Bext; }

    const int m0 = blockIdx.y * BM;
    const int n0 = blockIdx.x * BN;

    const int arow  = tid >> 1;          // 0..127
    const int akoff = (tid & 1) << 3;    // 0 or 8
    const int bn    = tid & 127;         // mode 4
    const int bhalf = tid >> 7;          // mode 4

    float fa[8], fb[8];

    auto ldg_stage = [&](int kt) {
        const float* ap = A + (size_t)(m0 + arow)*K + kt + akoff;
        float4 v0 = *reinterpret_cast<const float4*>(ap);
        float4 v1 = *reinterpret_cast<const float4*>(ap + 4);
        fa[0]=v0.x; fa[1]=v0.y; fa[2]=v0.z; fa[3]=v0.w;
        fa[4]=v1.x; fa[5]=v1.y; fa[6]=v1.z; fa[7]=v1.w;
        if constexpr (MODE == 4) {
#pragma unroll
            for (int j = 0; j < 8; j++)
                fb[j] = Bp[(size_t)(kt + 8*bhalf + j)*DHEAD + bn];
        } else {
            const float* bp = Bp + (size_t)(n0 + arow)*K + kt + akoff;
            float4 w0 = *reinterpret_cast<const float4*>(bp);
            float4 w1 = *reinterpret_cast<const float4*>(bp + 4);
            fb[0]=w0.x; fb[1]=w0.y; fb[2]=w0.z; fb[3]=w0.w;
            fb[4]=w1.x; fb[5]=w1.y; fb[6]=w1.z; fb[7]=w1.w;
        }
    };

    float acc[4][4][4];
#pragma unroll
    for (int i = 0; i < 4; i++)
#pragma unroll
        for (int j = 0; j < 4; j++)
#pragma unroll
            for (int f = 0; f < 4; f++) acc[i][j][f] = 0.f;

    const int iters = K / BK;
    ldg_stage(0);

    for (int it = 0; it < iters; ++it) {
        __syncthreads();   // previous mma done -> packed buffers free
        {
            unsigned ph[4], pl[4];
            cvt8(fa, ph, pl);
            *reinterpret_cast<uint4*>(&pAh[arow][akoff >> 1]) = make_uint4(ph[0],ph[1],ph[2],ph[3]);
            *reinterpret_cast<uint4*>(&pAl[arow][akoff >> 1]) = make_uint4(pl[0],pl[1],pl[2],pl[3]);
            cvt8(fb, ph, pl);
            if constexpr (MODE == 4) {
                *reinterpret_cast<uint4*>(&pBh[bn][4*bhalf]) = make_uint4(ph[0],ph[1],ph[2],ph[3]);
                *reinterpret_cast<uint4*>(&pBl[bn][4*bhalf]) = make_uint4(pl[0],pl[1],pl[2],pl[3]);
            } else {
                *reinterpret_cast<uint4*>(&pBh[arow][akoff >> 1]) = make_uint4(ph[0],ph[1],ph[2],ph[3]);
                *reinterpret_cast<uint4*>(&pBl[arow][akoff >> 1]) = make_uint4(pl[0],pl[1],pl[2],pl[3]);
            }
        }
        __syncthreads();   // packed ready

        if (it + 1 < iters) ldg_stage((it + 1) * BK);   // latency hidden under mma

        // fragments (logical unit permutation: memory units (2lc,2lc+1) == logical (lc, lc+4))
        uint2 a0[4], a1[4], b_h[4], b_l[4];
#pragma unroll
        for (int mt = 0; mt < 4; mt++) {
            const int r = wm*64 + mt*16 + lr;
            a0[mt] = *reinterpret_cast<const uint2*>(&pAh[r  ][2*lc]);
            a1[mt] = *reinterpret_cast<const uint2*>(&pAh[r+8][2*lc]);
        }
#pragma unroll
        for (int nt = 0; nt < 4; nt++) {
            const int c = wn*32 + nt*8 + lr;
            b_h[nt] = *reinterpret_cast<const uint2*>(&pBh[c][2*lc]);
            b_l[nt] = *reinterpret_cast<const uint2*>(&pBl[c][2*lc]);
        }
#pragma unroll
        for (int mt = 0; mt < 4; mt++)
#pragma unroll
            for (int nt = 0; nt < 4; nt++) {
                mmabf(acc[mt][nt], a0[mt].x, a1[mt].x, a0[mt].y, a1[mt].y, b_h[nt].x, b_h[nt].y);
                mmabf(acc[mt][nt], a0[mt].x, a1[mt].x, a0[mt].y, a1[mt].y, b_l[nt].x, b_l[nt].y);
            }
#pragma unroll
        for (int mt = 0; mt < 4; mt++) {
            const int r = wm*64 + mt*16 + lr;
            a0[mt] = *reinterpret_cast<const uint2*>(&pAl[r  ][2*lc]);
            a1[mt] = *reinterpret_cast<const uint2*>(&pAl[r+8][2*lc]);
        }
#pragma unroll
        for (int mt = 0; mt < 4; mt++)
#pragma unroll
            for (int nt = 0; nt < 4; nt++)
                mmabf(acc[mt][nt], a0[mt].x, a1[mt].x, a0[mt].y, a1[mt].y, b_h[nt].x, b_h[nt].y);
    }

    const int lc2 = (lane & 3) << 1;
#pragma unroll
    for (int mt = 0; mt < 4; mt++)
#pragma unroll
        for (int nt = 0; nt < 4; nt++) {
            const int mb = m0 + wm*64 + mt*16 + lr;
            const int nb = n0 + wn*32 + nt*8 + lc2;
            store_pair<MODE>(acc[mt][nt][0], acc[mt][nt][1], mb,   nb, z, bias, nullptr, Cext);
            store_pair<MODE>(acc[mt][nt][2], acc[mt][nt][3], mb+8, nb, z, bias, nullptr, Cext);
        }
}

// ---------------- launch ----------------
extern "C" void kernel_launch(void* const* d_in, const int* in_sizes, int n_in,
                              void* d_out, int out_size)
{
    const float* x_q      = (const float*)d_in[0];
    const float* x_kv     = (const float*)d_in[1];
    const float* W_head_w = (const float*)d_in[2];
    const float* W_head_b = (const float*)d_in[3];
    const float* W_v_w    = (const float*)d_in[4];
    const float* W_v_b    = (const float*)d_in[5];
    const float* W_out_w  = (const float*)d_in[6];
    const float* W_out_b  = (const float*)d_in[7];
    const float* rel_emb  = (const float*)d_in[8];
    const float* col_head = (const float*)d_in[9];
    const float* col_tail = (const float*)d_in[10];

    float* out_x  = (float*)d_out;                          // [32,512,1024]
    float* out_fr = out_x + (size_t)BATCH*SEQ*DMODEL;       // [256,512,512]

    // 1) learned column topology mask
    adj_kernel<<<dim3(SEQ, HEADS), 128>>>(col_head, col_tail);

    // 2) projections
    gemm_tf32<0><<<dim3(8, 128), 256>>>(x_q,  W_head_w, W_head_b, rel_emb, nullptr,
                                        BATCH*SEQ, DMODEL, DMODEL);
    gemm_tf32<1><<<dim3(8, 128), 256>>>(x_kv, W_head_w, W_head_b, rel_emb, nullptr,
                                        BATCH*SEQ, DMODEL, DMODEL);
    gemm_tf32<2><<<dim3(8, 128), 256>>>(x_kv, W_v_w,    W_v_b,    nullptr, nullptr,
                                        BATCH*SEQ, DMODEL, DMODEL);

    // 3) scores + mask  -> fr region of d_out (raw logits)
    gemm_tf32<3><<<dim3(4, 4, BHS), 256>>>(nullptr, nullptr, nullptr, nullptr, out_fr,
                                           SEQ, SEQ, DHEAD);

    // 4) softmax rows in place
    softmax_rows<<<BHS*SEQ, 128>>>(out_fr);

    // 5) attention output = P @ V   (bf16 3-split)
    gemm_split<4><<<dim3(1, 4, BHS), 256>>>(out_fr, nullptr, nullptr, nullptr, SEQ);

    // 6) output projection           (bf16 3-split)
    gemm_split<5><<<dim3(8, 128), 256>>>(nullptr, W_out_w, W_out_b, out_x, DMODEL);
}

// round 5
// speedup vs baseline: 1.9161x; 1.1634x over previous
#include <cuda_runtime.h>
#include <cuda_bf16.h>
#include <math.h>
#include <cstdint>

#define BATCH   32
#define HEADS   8
#define SEQ     512
#define DMODEL  1024
#define DHEAD   128
#define DCOL    18
#define BHS     (BATCH*HEADS)   // 256
#define BSD     ((size_t)BATCH*SEQ*DMODEL)   // 16777216

// ---------------- scratch (static device globals; no allocation) ----------------
__device__ __align__(256) __nv_bfloat16 g_xqh[BSD], g_xql[BSD];
__device__ __align__(256) __nv_bfloat16 g_xkh[BSD], g_xkl[BSD];
__device__ __align__(256) __nv_bfloat16 g_Whh[DMODEL*DMODEL], g_Whl[DMODEL*DMODEL];
__device__ __align__(256) __nv_bfloat16 g_Wvh[DMODEL*DMODEL], g_Wvl[DMODEL*DMODEL];
__device__ __align__(256) __nv_bfloat16 g_Woh[DMODEL*DMODEL], g_Wol[DMODEL*DMODEL];
__device__ __align__(256) __nv_bfloat16 g_fhh[BSD], g_fhl[BSD];   // f_head hi/lo [b,h,q,dh]
__device__ __align__(256) __nv_bfloat16 g_fth[BSD], g_ftl[BSD];   // f_tail hi/lo [b,h,k,dh]
__device__ __align__(256) float        g_fv [BSD];                 // f_v fp32 [b,h,k,dh]
__device__ __align__(256) __nv_bfloat16 g_ath[BSD], g_atl[BSD];    // attn hi/lo [b,q,h*dh]
__device__ __align__(256) float        g_adjm[(size_t)HEADS*SEQ*SEQ];

// ---------------- small helpers ----------------
__device__ __forceinline__ unsigned packbf(float f0, float f1) {   // f0 -> low half
    unsigned d;
    asm("cvt.rn.bf16x2.f32 %0, %1, %2;" : "=r"(d) : "f"(f1), "f"(f0));
    return d;
}
__device__ __forceinline__ float bf_lo(unsigned p) { return __uint_as_float(p << 16); }
__device__ __forceinline__ float bf_up(unsigned p) { return __uint_as_float(p & 0xFFFF0000u); }

__device__ __forceinline__ unsigned smem_u32(const void* p) {
    unsigned a;
    asm("{ .reg .u64 t; cvta.to.shared.u64 t, %1; cvt.u32.u64 %0, t; }" : "=r"(a) : "l"(p));
    return a;
}
__device__ __forceinline__ void cpa16s(unsigned dst, const void* src) {
    asm volatile("cp.async.ca.shared.global [%0], [%1], 16;" :: "r"(dst), "l"(src));
}
__device__ __forceinline__ void cpa_commit() { asm volatile("cp.async.commit_group;"); }
template<int N>
__device__ __forceinline__ void cpa_wait() { asm volatile("cp.async.wait_group %0;" :: "n"(N)); }

__device__ __forceinline__ void ldm4(unsigned& r0, unsigned& r1, unsigned& r2, unsigned& r3,
                                     unsigned addr) {
    asm volatile("ldmatrix.sync.aligned.m8n8.x4.shared.b16 {%0,%1,%2,%3}, [%4];"
                 : "=r"(r0), "=r"(r1), "=r"(r2), "=r"(r3) : "r"(addr));
}

__device__ __forceinline__ void mmabf(float* c, unsigned a0, unsigned a1, unsigned a2,
                                      unsigned a3, unsigned b0, unsigned b1) {
    asm volatile(
        "mma.sync.aligned.m16n8k16.row.col.f32.bf16.bf16.f32 "
        "{%0,%1,%2,%3}, {%4,%5,%6,%7}, {%8,%9}, {%0,%1,%2,%3};\n"
        : "+f"(c[0]), "+f"(c[1]), "+f"(c[2]), "+f"(c[3])
        : "r"(a0), "r"(a1), "r"(a2), "r"(a3), "r"(b0), "r"(b1));
}

__device__ __forceinline__ void cvt8(const float* f, unsigned* ph, unsigned* pl) {
#pragma unroll
    for (int j = 0; j < 4; j++) {
        unsigned h = packbf(f[2*j], f[2*j+1]);
        ph[j] = h;
        pl[j] = packbf(f[2*j] - bf_lo(h), f[2*j+1] - bf_up(h));
    }
}

// ---------------- fp32 -> bf16 hi/lo conversion (W selects destination) ----------------
template<int W>
__global__ void cvt_hilo(const float* __restrict__ src, int n4)
{
    __nv_bfloat16 *hi, *lo;
    if constexpr (W == 0) { hi = g_xqh; lo = g_xql; }
    else if constexpr (W == 1) { hi = g_xkh; lo = g_xkl; }
    else if constexpr (W == 2) { hi = g_Whh; lo = g_Whl; }
    else if constexpr (W == 3) { hi = g_Wvh; lo = g_Wvl; }
    else                       { hi = g_Woh; lo = g_Wol; }
    uint2* hu = reinterpret_cast<uint2*>(hi);
    uint2* lu = reinterpret_cast<uint2*>(lo);
    const float4* s4 = reinterpret_cast<const float4*>(src);
    for (int i = blockIdx.x * blockDim.x + threadIdx.x; i < n4; i += gridDim.x * blockDim.x) {
        float4 v = s4[i];
        unsigned h0 = packbf(v.x, v.y), h1 = packbf(v.z, v.w);
        unsigned l0 = packbf(v.x - bf_lo(h0), v.y - bf_up(h0));
        unsigned l1 = packbf(v.z - bf_lo(h1), v.w - bf_up(h1));
        hu[i] = make_uint2(h0, h1);
        lu[i] = make_uint2(l0, l1);
    }
}

// ---------------- adjacency: softmax(col_head @ col_tail^T, diag=0) ----------------
__global__ void adj_kernel(const float* __restrict__ col_head,
                           const float* __restrict__ col_tail)
{
    const int q = blockIdx.x;
    const int h = blockIdx.y;
    const int t = threadIdx.x;                 // 128 threads
    __shared__ float ch[DCOL];
    __shared__ float sred[4];

    if (t < DCOL) ch[t] = col_head[((size_t)h*SEQ + q)*DCOL + t];
    __syncthreads();

    float l[4];
#pragma unroll
    for (int i = 0; i < 4; i++) {
        const int k = t + i*128;
        const float* ct = col_tail + ((size_t)h*SEQ + k)*DCOL;
        float s = 0.f;
#pragma unroll
        for (int c = 0; c < DCOL; c++) s += ch[c]*ct[c];
        l[i] = (k == q) ? 0.f : s;
    }

    float mx = fmaxf(fmaxf(l[0],l[1]), fmaxf(l[2],l[3]));
#pragma unroll
    for (int o = 16; o; o >>= 1) mx = fmaxf(mx, __shfl_xor_sync(0xffffffffu, mx, o));
    if ((t & 31) == 0) sred[t >> 5] = mx;
    __syncthreads();
    mx = fmaxf(fmaxf(sred[0],sred[1]), fmaxf(sred[2],sred[3]));
    __syncthreads();

    float e[4]; float sum = 0.f;
#pragma unroll
    for (int i = 0; i < 4; i++) { e[i] = expf(l[i]-mx); sum += e[i]; }
#pragma unroll
    for (int o = 16; o; o >>= 1) sum += __shfl_xor_sync(0xffffffffu, sum, o);
    if ((t & 31) == 0) sred[t >> 5] = sum;
    __syncthreads();
    sum = sred[0]+sred[1]+sred[2]+sred[3];
    const float inv = 1.f/sum;

    float* dst = g_adjm + ((size_t)h*SEQ + q)*SEQ;
#pragma unroll
    for (int i = 0; i < 4; i++) {
        const int k = t + i*128;
        dst[k] = (1.f - e[i]*inv) * (-10000.f);
    }
}

// ---------------- row softmax over fr_graph ----------------
__global__ void softmax_rows(float* __restrict__ fr)
{
    const int t = threadIdx.x;                  // 128 threads, float4 each
    float* rowp = fr + (size_t)blockIdx.x * SEQ;
    __shared__ float sred[4];

    float4 v = reinterpret_cast<float4*>(rowp)[t];
    float mx = fmaxf(fmaxf(v.x, v.y), fmaxf(v.z, v.w));
#pragma unroll
    for (int o = 16; o; o >>= 1) mx = fmaxf(mx, __shfl_xor_sync(0xffffffffu, mx, o));
    if ((t & 31) == 0) sred[t >> 5] = mx;
    __syncthreads();
    mx = fmaxf(fmaxf(sred[0],sred[1]), fmaxf(sred[2],sred[3]));
    __syncthreads();

    v.x = expf(v.x - mx); v.y = expf(v.y - mx);
    v.z = expf(v.z - mx); v.w = expf(v.w - mx);
    float s = v.x + v.y + v.z + v.w;
#pragma unroll
    for (int o = 16; o; o >>= 1) s += __shfl_xor_sync(0xffffffffu, s, o);
    if ((t & 31) == 0) sred[t >> 5] = s;
    __syncthreads();
    s = sred[0]+sred[1]+sred[2]+sred[3];
    const float inv = 1.f/s;
    v.x *= inv; v.y *= inv; v.z *= inv; v.w *= inv;
    reinterpret_cast<float4*>(rowp)[t] = v;
}

// ---------------- mode epilogue: contiguous (n, n+1) pair ----------------
// MODE 0: f_head -> g_fhh/g_fhl, (acc+bias)*rel_emb, bf16 hi/lo
// MODE 1: f_tail -> g_fth/g_ftl, same
// MODE 2: f_v    -> g_fv fp32, acc+bias
// MODE 3: scores -> Cext fp32, acc/sqrt(dh)+adjm
// MODE 5: outproj-> Cext fp32, acc+bias
template<int MODE>
__device__ __forceinline__ void store_pair(float v0, float v1, int m, int n, int z,
    const float* __restrict__ bias, const float* __restrict__ aux,
    float* __restrict__ Cext)
{
    if constexpr (MODE == 0 || MODE == 1) {
        v0 = (v0 + bias[n]) * aux[n];
        v1 = (v1 + bias[n+1]) * aux[n+1];
        const int b = m >> 9, q = m & 511, h = n >> 7, dh = n & 127;
        const size_t idx = (((size_t)((b<<3)|h))*SEQ + q)*DHEAD + dh;  // even
        const unsigned ph = packbf(v0, v1);
        const unsigned pl = packbf(v0 - bf_lo(ph), v1 - bf_up(ph));
        __nv_bfloat16* dh_a = (MODE == 0) ? g_fhh : g_fth;
        __nv_bfloat16* dl_a = (MODE == 0) ? g_fhl : g_ftl;
        *reinterpret_cast<unsigned*>(&dh_a[idx]) = ph;
        *reinterpret_cast<unsigned*>(&dl_a[idx]) = pl;
    } else if constexpr (MODE == 2) {
        const int b = m >> 9, q = m & 511, h = n >> 7, dh = n & 127;
        float2 o; o.x = v0 + bias[n]; o.y = v1 + bias[n+1];
        *reinterpret_cast<float2*>(&g_fv[(((size_t)((b<<3)|h))*SEQ + q)*DHEAD + dh]) = o;
    } else if constexpr (MODE == 3) {
        const int h = z & 7;
        const size_t off = (size_t)m*SEQ + n;
        float2 am = *reinterpret_cast<const float2*>(&g_adjm[(size_t)h*SEQ*SEQ + off]);
        float2 o;
        o.x = v0 * 0.08838834764831845f + am.x;
        o.y = v1 * 0.08838834764831845f + am.y;
        *reinterpret_cast<float2*>(&Cext[(size_t)z*SEQ*SEQ + off]) = o;
    } else {
        float2 o; o.x = v0 + bias[n]; o.y = v1 + bias[n+1];
        *reinterpret_cast<float2*>(&Cext[(size_t)m*DMODEL + n]) = o;
    }
}

// ---------------- bf16 3-term ldmatrix GEMM: C = A[M,K] @ B[N,K]^T ----------------
#define LDK    40                 // padded smem row (bf16 elems), 80 bytes
#define TILEB  (128*LDK*2)        // 10240 B per tile
#define STAGEB (4*TILEB)          // Ah, Al, Bh, Bl
#define BFG_DSM (2*STAGEB)        // 81920 B

template<int MODE>
__global__ void __launch_bounds__(256, 2)
bf_gemm(const float* __restrict__ bias, const float* __restrict__ aux,
        float* __restrict__ Cext, int K)
{
    extern __shared__ char sm[];
    const unsigned sbase = smem_u32(sm);

    const int tid  = threadIdx.x;
    const int lane = tid & 31;
    const int warp = tid >> 5;
    const int wm   = warp >> 2, wn = warp & 3;
    const int z    = blockIdx.z;
    const int m0   = blockIdx.y * 128;
    const int n0   = blockIdx.x * 128;

    const __nv_bfloat16 *Ah, *Al, *Bh, *Bl;
    if constexpr (MODE == 0)      { Ah=g_xqh; Al=g_xql; Bh=g_Whh; Bl=g_Whl; }
    else if constexpr (MODE == 1) { Ah=g_xkh; Al=g_xkl; Bh=g_Whh; Bl=g_Whl; }
    else if constexpr (MODE == 2) { Ah=g_xkh; Al=g_xkl; Bh=g_Wvh; Bl=g_Wvl; }
    else if constexpr (MODE == 3) {
        Ah = g_fhh + (size_t)z*SEQ*DHEAD;  Al = g_fhl + (size_t)z*SEQ*DHEAD;
        Bh = g_fth + (size_t)z*SEQ*DHEAD;  Bl = g_ftl + (size_t)z*SEQ*DHEAD;
    } else {
        Ah = g_ath; Al = g_atl; Bh = g_Woh; Bl = g_Wol;
    }

    auto load_stage = [&](int st, int kt) {
        const unsigned sb = sbase + st*STAGEB;
#pragma unroll
        for (int i = 0; i < 8; i++) {
            const int idx  = tid + i*256;          // 0..2047 chunks
            const int tile = idx >> 9;             // 0:Ah 1:Al 2:Bh 3:Bl
            const int r    = (idx >> 2) & 127;
            const int c    = idx & 3;              // 16B chunk within 64B row
            const __nv_bfloat16* s = (tile == 0) ? Ah : (tile == 1) ? Al :
                                     (tile == 2) ? Bh : Bl;
            const int rg = ((tile < 2) ? m0 : n0) + r;
            cpa16s(sb + tile*TILEB + r*(LDK*2) + c*16,
                   s + (size_t)rg*K + kt + c*8);
        }
    };

    float acc[4][4][4];
#pragma unroll
    for (int i = 0; i < 4; i++)
#pragma unroll
        for (int j = 0; j < 4; j++)
#pragma unroll
            for (int f = 0; f < 4; f++) acc[i][j][f] = 0.f;

    // ldmatrix lane geometry
    const int rowA = (lane & 7) + ((lane >> 3) & 1) * 8;
    const int colA = ((lane >> 4) & 1) * 8;
    const int rowB = (lane & 7) + ((lane >> 4) & 1) * 8;
    const int colB = ((lane >> 3) & 1) * 8;

    const int iters = K >> 5;
    load_stage(0, 0);
    cpa_commit();

    for (int it = 0; it < iters; ++it) {
        const int cur = it & 1;
        if (it + 1 < iters) { load_stage(cur ^ 1, (it + 1) << 5); cpa_commit(); cpa_wait<1>(); }
        else                { cpa_wait<0>(); }
        __syncthreads();

        const unsigned sb  = sbase + cur*STAGEB;
        const unsigned aAh = sb + (wm*64 + rowA)*(LDK*2) + colA*2;
        const unsigned aAl = aAh + TILEB;
        const unsigned aBh = sb + 2*TILEB + (wn*32 + rowB)*(LDK*2) + colB*2;
        const unsigned aBl = aBh + TILEB;

#pragma unroll
        for (int ks = 0; ks < 2; ks++) {
            const unsigned ko = ks*32;   // 16 bf16 = 32 bytes
            unsigned bh[4][2], bl[4][2];
#pragma unroll
            for (int p = 0; p < 2; p++) {
                unsigned r0, r1, r2, r3;
                ldm4(r0, r1, r2, r3, aBh + p*16*(LDK*2) + ko);
                bh[2*p][0]=r0; bh[2*p][1]=r1; bh[2*p+1][0]=r2; bh[2*p+1][1]=r3;
                ldm4(r0, r1, r2, r3, aBl + p*16*(LDK*2) + ko);
                bl[2*p][0]=r0; bl[2*p][1]=r1; bl[2*p+1][0]=r2; bl[2*p+1][1]=r3;
            }
#pragma unroll
            for (int mt = 0; mt < 4; mt++) {
                unsigned a[4], al_[4];
                ldm4(a[0], a[1], a[2], a[3],     aAh + mt*16*(LDK*2) + ko);
                ldm4(al_[0], al_[1], al_[2], al_[3], aAl + mt*16*(LDK*2) + ko);
#pragma unroll
                for (int nt = 0; nt < 4; nt++) {
                    mmabf(acc[mt][nt], a[0],a[1],a[2],a[3],     bh[nt][0], bh[nt][1]);
                    mmabf(acc[mt][nt], a[0],a[1],a[2],a[3],     bl[nt][0], bl[nt][1]);
                    mmabf(acc[mt][nt], al_[0],al_[1],al_[2],al_[3], bh[nt][0], bh[nt][1]);
                }
            }
        }
        __syncthreads();
    }

    const int lr2 = lane >> 2;
    const int lc2 = (lane & 3) << 1;
#pragma unroll
    for (int mt = 0; mt < 4; mt++)
#pragma unroll
        for (int nt = 0; nt < 4; nt++) {
            const int mb = m0 + wm*64 + mt*16 + lr2;
            const int nb = n0 + wn*32 + nt*8 + lc2;
            store_pair<MODE>(acc[mt][nt][0], acc[mt][nt][1], mb,   nb, z, bias, aux, Cext);
            store_pair<MODE>(acc[mt][nt][2], acc[mt][nt][3], mb+8, nb, z, bias, aux, Cext);
        }
}

// ---------------- bf16 3-split GEMM for P @ V  (A fp32 converted in-loop) ----------------
__global__ void __launch_bounds__(256, 2)
gemm_pv(const float* __restrict__ Aext, int K)
{
    constexpr int BM = 128, PPAD = 12;
    __shared__ __align__(16) unsigned pAh[BM][PPAD];
    __shared__ __align__(16) unsigned pAl[BM][PPAD];
    __shared__ __align__(16) unsigned pBh[128][PPAD];
    __shared__ __align__(16) unsigned pBl[128][PPAD];

    const int tid  = threadIdx.x;
    const int lane = tid & 31;
    const int warp = tid >> 5;
    const int wm   = warp >> 2, wn = warp & 3;
    const int lr   = lane >> 2, lc = lane & 3;
    const int z    = blockIdx.z;

    const float* A  = Aext + (size_t)z*SEQ*SEQ;
    const float* Bp = g_fv + (size_t)z*SEQ*DHEAD;

    const int m0 = blockIdx.y * BM;

    const int arow  = tid >> 1;
    const int akoff = (tid & 1) << 3;
    const int bn    = tid & 127;
    const int bhalf = tid >> 7;

    float fa[8], fb[8];

    auto ldg_stage = [&](int kt) {
        const float* ap = A + (size_t)(m0 + arow)*K + kt + akoff;
        float4 v0 = *reinterpret_cast<const float4*>(ap);
        float4 v1 = *reinterpret_cast<const float4*>(ap + 4);
        fa[0]=v0.x; fa[1]=v0.y; fa[2]=v0.z; fa[3]=v0.w;
        fa[4]=v1.x; fa[5]=v1.y; fa[6]=v1.z; fa[7]=v1.w;
#pragma unroll
        for (int j = 0; j < 8; j++)
            fb[j] = Bp[(size_t)(kt + 8*bhalf + j)*DHEAD + bn];
    };

    float acc[4][4][4];
#pragma unroll
    for (int i = 0; i < 4; i++)
#pragma unroll
        for (int j = 0; j < 4; j++)
#pragma unroll
            for (int f = 0; f < 4; f++) acc[i][j][f] = 0.f;

    const int iters = K / 16;
    ldg_stage(0);

    for (int it = 0; it < iters; ++it) {
        __syncthreads();
        {
            unsigned ph[4], pl[4];
            cvt8(fa, ph, pl);
            *reinterpret_cast<uint4*>(&pAh[arow][akoff >> 1]) = make_uint4(ph[0],ph[1],ph[2],ph[3]);
            *reinterpret_cast<uint4*>(&pAl[arow][akoff >> 1]) = make_uint4(pl[0],pl[1],pl[2],pl[3]);
            cvt8(fb, ph, pl);
            *reinterpret_cast<uint4*>(&pBh[bn][4*bhalf]) = make_uint4(ph[0],ph[1],ph[2],ph[3]);
            *reinterpret_cast<uint4*>(&pBl[bn][4*bhalf]) = make_uint4(pl[0],pl[1],pl[2],pl[3]);
        }
        __syncthreads();

        if (it + 1 < iters) ldg_stage((it + 1) * 16);

        uint2 a0[4], a1[4], b_h[4], b_l[4];
#pragma unroll
        for (int mt = 0; mt < 4; mt++) {
            const int r = wm*64 + mt*16 + lr;
            a0[mt] = *reinterpret_cast<const uint2*>(&pAh[r  ][2*lc]);
            a1[mt] = *reinterpret_cast<const uint2*>(&pAh[r+8][2*lc]);
        }
#pragma unroll
        for (int nt = 0; nt < 4; nt++) {
            const int c = wn*32 + nt*8 + lr;
            b_h[nt] = *reinterpret_cast<const uint2*>(&pBh[c][2*lc]);
            b_l[nt] = *reinterpret_cast<const uint2*>(&pBl[c][2*lc]);
        }
#pragma unroll
        for (int mt = 0; mt < 4; mt++)
#pragma unroll
            for (int nt = 0; nt < 4; nt++) {
                mmabf(acc[mt][nt], a0[mt].x, a1[mt].x, a0[mt].y, a1[mt].y, b_h[nt].x, b_h[nt].y);
                mmabf(acc[mt][nt], a0[mt].x, a1[mt].x, a0[mt].y, a1[mt].y, b_l[nt].x, b_l[nt].y);
            }
#pragma unroll
        for (int mt = 0; mt < 4; mt++) {
            const int r = wm*64 + mt*16 + lr;
            a0[mt] = *reinterpret_cast<const uint2*>(&pAl[r  ][2*lc]);
            a1[mt] = *reinterpret_cast<const uint2*>(&pAl[r+8][2*lc]);
        }
#pragma unroll
        for (int mt = 0; mt < 4; mt++)
#pragma unroll
            for (int nt = 0; nt < 4; nt++)
                mmabf(acc[mt][nt], a0[mt].x, a1[mt].x, a0[mt].y, a1[mt].y, b_h[nt].x, b_h[nt].y);
    }

    // epilogue: emit attn hi/lo bf16 pairs
    const int b = z >> 3, h = z & 7;
    const int lc2 = (lane & 3) << 1;
#pragma unroll
    for (int mt = 0; mt < 4; mt++)
#pragma unroll
        for (int nt = 0; nt < 4; nt++) {
            const int mb = m0 + wm*64 + mt*16 + lr;
            const int nb = wn*32 + nt*8 + lc2;
#pragma unroll
            for (int hh = 0; hh < 2; hh++) {
                const float v0 = acc[mt][nt][hh*2+0];
                const float v1 = acc[mt][nt][hh*2+1];
                const size_t idx = ((size_t)(b*SEQ + mb + hh*8))*DMODEL + h*DHEAD + nb;
                const unsigned ph = packbf(v0, v1);
                const unsigned pl = packbf(v0 - bf_lo(ph), v1 - bf_up(ph));
                *reinterpret_cast<unsigned*>(&g_ath[idx]) = ph;
                *reinterpret_cast<unsigned*>(&g_atl[idx]) = pl;
            }
        }
}

// ---------------- launch ----------------
extern "C" void kernel_launch(void* const* d_in, const int* in_sizes, int n_in,
                              void* d_out, int out_size)
{
    const float* x_q      = (const float*)d_in[0];
    const float* x_kv     = (const float*)d_in[1];
    const float* W_head_w = (const float*)d_in[2];
    const float* W_head_b = (const float*)d_in[3];
    const float* W_v_w    = (const float*)d_in[4];
    const float* W_v_b    = (const float*)d_in[5];
    const float* W_out_w  = (const float*)d_in[6];
    const float* W_out_b  = (const float*)d_in[7];
    const float* rel_emb  = (const float*)d_in[8];
    const float* col_head = (const float*)d_in[9];
    const float* col_tail = (const float*)d_in[10];

    float* out_x  = (float*)d_out;                          // [32,512,1024]
    float* out_fr = out_x + (size_t)BATCH*SEQ*DMODEL;       // [256,512,512]

    static bool attr_done = false;
    if (!attr_done) {
        cudaFuncSetAttribute(bf_gemm<0>, cudaFuncAttributeMaxDynamicSharedMemorySize, BFG_DSM);
        cudaFuncSetAttribute(bf_gemm<1>, cudaFuncAttributeMaxDynamicSharedMemorySize, BFG_DSM);
        cudaFuncSetAttribute(bf_gemm<2>, cudaFuncAttributeMaxDynamicSharedMemorySize, BFG_DSM);
        cudaFuncSetAttribute(bf_gemm<3>, cudaFuncAttributeMaxDynamicSharedMemorySize, BFG_DSM);
        cudaFuncSetAttribute(bf_gemm<5>, cudaFuncAttributeMaxDynamicSharedMemorySize, BFG_DSM);
        attr_done = true;
    }

    // 0) pre-convert inputs to bf16 hi/lo
    cvt_hilo<0><<<2048, 256>>>(x_q,      (int)(BSD/4));
    cvt_hilo<1><<<2048, 256>>>(x_kv,     (int)(BSD/4));
    cvt_hilo<2><<<1024, 256>>>(W_head_w, DMODEL*DMODEL/4);
    cvt_hilo<3><<<1024, 256>>>(W_v_w,    DMODEL*DMODEL/4);
    cvt_hilo<4><<<1024, 256>>>(W_out_w,  DMODEL*DMODEL/4);

    // 1) learned column topology mask
    adj_kernel<<<dim3(SEQ, HEADS), 128>>>(col_head, col_tail);

    // 2) projections
    bf_gemm<0><<<dim3(8, 128), 256, BFG_DSM>>>(W_head_b, rel_emb, nullptr, DMODEL);
    bf_gemm<1><<<dim3(8, 128), 256, BFG_DSM>>>(W_head_b, rel_emb, nullptr, DMODEL);
    bf_gemm<2><<<dim3(8, 128), 256, BFG_DSM>>>(W_v_b,    nullptr, nullptr, DMODEL);

    // 3) scores + mask -> fr region of d_out (raw logits)
    bf_gemm<3><<<dim3(4, 4, BHS), 256, BFG_DSM>>>(nullptr, nullptr, out_fr, DHEAD);

    // 4) softmax rows in place
    softmax_rows<<<BHS*SEQ, 128>>>(out_fr);

    // 5) attention output = P @ V -> attn hi/lo
    gemm_pv<<<dim3(1, 4, BHS), 256>>>(out_fr, SEQ);

    // 6) output projection
    bf_gemm<5><<<dim3(8, 128), 256, BFG_DSM>>>(W_out_b, nullptr, out_x, DMODEL);
}